// round 13
// baseline (speedup 1.0000x reference)
#include <cuda_runtime.h>
#include <cuda_bf16.h>

#define BB 32
#define TT 1024
#define HH 384
#define MEL 4096
#define H4 (HH/4)   // 96 float4 per frame
#define ZB 128      // zerofill role-blocks per batch
#define NT 96       // threads per block

// scratch (allocation-free rule: device globals)
__device__ int g_start[BB * TT];           // exclusive cumsum of reps
__device__ int g_dec[BB];
__device__ unsigned int g_flag[BB] = {0};  // per-batch release (monotonic, replay-safe)

// ---------------------------------------------------------------------------
// Single fused kernel. grid = (1 + TT + ZB, BB)  [x-major => write locality]
//   blockIdx.x == 0          : prep role for batch b (lowest ID in batch slice)
//   1 <= blockIdx.x <= TT    : token expansion for t = x-1 (spin on flag[b])
//   blockIdx.x >  TT         : zerofill of [dec_len, MEL), strided (spin)
// ---------------------------------------------------------------------------
__global__ void __launch_bounds__(NT) fused_kernel(
    const float* __restrict__ enc,     // [B,T,H]
    const float* __restrict__ pitch,   // [B,1,T]
    const float* __restrict__ energy,  // [B,1,T]
    const float* __restrict__ pw,      // [H,1,3]
    const float* __restrict__ pb,      // [H]
    const float* __restrict__ ew,      // [H,1,3]
    const float* __restrict__ eb,      // [H]
    const int*   __restrict__ durations,
    float* __restrict__ out,           // [B,MEL,H]
    float* __restrict__ out_tail)      // [B] dec_lens (may be null)
{
    const int b = blockIdx.y;
    const int role = blockIdx.x;
    const int tidx = threadIdx.x;

    // ======================== prep role =====================================
    if (role == 0) {
        // thread i owns int4 chunks 3i..3i+2 (tokens 12i .. 12i+11); 96*3=288>=256
        const int4* din = (const int4*)(durations + b * TT);
        int4 c[3];
        int  cs[3];
        int  local = 0;
        #pragma unroll
        for (int k = 0; k < 3; ++k) {
            const int ci = 3 * tidx + k;
            if (ci < 256) {
                int4 d = din[ci];
                c[k] = d;
                cs[k] = d.x + d.y + d.z + d.w;
            } else {
                c[k] = make_int4(0, 0, 0, 0);
                cs[k] = 0;
            }
            local += cs[k];
        }

        // inclusive scan of per-thread sums over 96 threads (3 warps)
        const int lane = tidx & 31;
        const int wid  = tidx >> 5;
        int v = local;
        #pragma unroll
        for (int o = 1; o < 32; o <<= 1) {
            int n = __shfl_up_sync(0xFFFFFFFFu, v, o);
            if (lane >= o) v += n;
        }
        __shared__ int wsum[3];
        if (lane == 31) wsum[wid] = v;
        __syncthreads();
        int wbase = 0;
        if (wid >= 1) wbase += wsum[0];
        if (wid >= 2) wbase += wsum[1];

        int base = wbase + v - local;   // exclusive prefix at token 12*tidx

        #pragma unroll
        for (int k = 0; k < 3; ++k) {
            const int ci = 3 * tidx + k;
            if (ci < 256) {
                int4 st;
                st.x = base;
                st.y = st.x + c[k].x;
                st.z = st.y + c[k].y;
                st.w = st.z + c[k].z;
                ((int4*)(g_start + b * TT))[ci] = st;
            }
            base += cs[k];
        }

        if (tidx == NT - 1) {
            const int dlen = min(base, MEL);   // base == batch total here
            g_dec[b] = dlen;
            if (out_tail) out_tail[b] = (float)dlen;
        }

        __threadfence();
        __syncthreads();
        if (tidx == 0) atomicAdd(&g_flag[b], 1u);   // release (monotonic)
        return;
    }

    const int q = tidx;

    // ======================== zerofill role ================================
    if (role > TT) {
        const int z = role - 1 - TT;
        const float4 zero = make_float4(0.f, 0.f, 0.f, 0.f);
        float4* base = (float4*)out + (long long)b * MEL * H4 + q;
        unsigned f;
        do {
            asm volatile("ld.acquire.gpu.u32 %0, [%1];" : "=r"(f) : "l"(&g_flag[b]) : "memory");
            if (f != 0u) break;
            __nanosleep(32);
        } while (true);
        const int dec = g_dec[b];
        for (int j = dec + z; j < MEL; j += ZB)
            __stcs(base + (long long)j * H4, zero);
        return;
    }

    // ======================== token expansion role =========================
    const int t = role - 1;
    const int rep = durations[b * TT + t];          // input, prep-independent
    if (rep <= 0) return;

    // ---- prep-independent prologue (overlaps the prep blocks' work) ----
    const float4 e4 = *(const float4*)(enc + ((long long)b * TT + t) * HH + 4 * q);

    const float* pr = pitch  + (long long)b * TT;
    const float* er = energy + (long long)b * TT;
    const float pm1 = (t > 0)      ? pr[t - 1] : 0.f;
    const float p0  =                pr[t];
    const float pp1 = (t < TT - 1) ? pr[t + 1] : 0.f;
    const float em1 = (t > 0)      ? er[t - 1] : 0.f;
    const float e0  =                er[t];
    const float ep1 = (t < TT - 1) ? er[t + 1] : 0.f;

    const float4* pwv = (const float4*)(pw + 12 * q);
    const float4 w0 = pwv[0], w1 = pwv[1], w2 = pwv[2];
    const float4* ewv = (const float4*)(ew + 12 * q);
    const float4 u0 = ewv[0], u1 = ewv[1], u2 = ewv[2];
    const float4 pbv = ((const float4*)pb)[q];
    const float4 ebv = ((const float4*)eb)[q];

    float4 res;
    res.x = e4.x + pbv.x + ebv.x
          + pm1 * w0.x + p0 * w0.y + pp1 * w0.z
          + em1 * u0.x + e0 * u0.y + ep1 * u0.z;
    res.y = e4.y + pbv.y + ebv.y
          + pm1 * w0.w + p0 * w1.x + pp1 * w1.y
          + em1 * u0.w + e0 * u1.x + ep1 * u1.y;
    res.z = e4.z + pbv.z + ebv.z
          + pm1 * w1.z + p0 * w1.w + pp1 * w2.x
          + em1 * u1.z + e0 * u1.w + ep1 * u2.x;
    res.w = e4.w + pbv.w + ebv.w
          + pm1 * w2.y + p0 * w2.z + pp1 * w2.w
          + em1 * u2.y + e0 * u2.z + ep1 * u2.w;

    // ---- acquire-spin on own batch's flag, then read start and store ----
    {
        unsigned f;
        do {
            asm volatile("ld.acquire.gpu.u32 %0, [%1];" : "=r"(f) : "l"(&g_flag[b]) : "memory");
            if (f != 0u) break;
            __nanosleep(32);
        } while (true);
    }
    const int start = g_start[b * TT + t];
    const int n = min(start + rep, MEL) - start;
    if (n <= 0) return;

    // predicated store burst: reps < 8, all addresses independent
    float4* dst = (float4*)out + ((long long)b * MEL + start) * H4 + q;
    #pragma unroll
    for (int j = 0; j < 7; ++j)
        if (j < n) __stcs(dst + (long long)j * H4, res);
    for (int j = 7; j < n; ++j)          // safety; never taken for this data
        __stcs(dst + (long long)j * H4, res);
}

extern "C" void kernel_launch(void* const* d_in, const int* in_sizes, int n_in,
                              void* d_out, int out_size)
{
    const float* enc    = (const float*)d_in[0];
    const float* pitch  = (const float*)d_in[1];
    const float* energy = (const float*)d_in[2];
    const float* pw     = (const float*)d_in[3];
    const float* pb     = (const float*)d_in[4];
    const float* ew     = (const float*)d_in[5];
    const float* eb     = (const float*)d_in[6];
    const int*   dur    = (const int*)d_in[7];
    float* out = (float*)d_out;

    const long long mainN = (long long)BB * MEL * HH;    // 50,331,648
    float* out_tail = ((long long)out_size >= mainN + BB) ? (out + mainN) : nullptr;

    dim3 grid(1 + TT + ZB, BB);
    fused_kernel<<<grid, NT>>>(enc, pitch, energy, pw, pb, ew, eb, dur, out, out_tail);
}

// round 14
// speedup vs baseline: 1.5835x; 1.5835x over previous
#include <cuda_runtime.h>
#include <cuda_bf16.h>

#define BB 32
#define TT 1024
#define HH 384
#define MEL 4096
#define H4 (HH/4)   // 96 float4 per frame
#define ZB 128      // zerofill blocks per batch (appended to expand grid)
#define PT 256      // prep threads (each handles 4 tokens via int4)

// scratch (allocation-free rule: device globals)
__device__ int g_start[BB * TT];   // exclusive cumsum of reps
__device__ int g_dec[BB];

// ---------------------------------------------------------------------------
// Kernel 1: per-batch scan -> start offsets, dec_lens, and the output tail.
// 256 threads, int4-vectorized: thread i owns tokens [4i, 4i+4).
// ---------------------------------------------------------------------------
__global__ void __launch_bounds__(PT) prep_kernel(const int* __restrict__ durations,
                                                  float* __restrict__ out_tail)
{
    const int b = blockIdx.x;
    const int i = threadIdx.x;
    const int lane = i & 31;
    const int wid  = i >> 5;

    int4 d = ((const int4*)(durations + b * TT))[i];
    if (d.x < 0) d.x = 0;
    if (d.y < 0) d.y = 0;
    if (d.z < 0) d.z = 0;
    if (d.w < 0) d.w = 0;
    const int local = d.x + d.y + d.z + d.w;

    // warp inclusive scan of per-thread sums
    int v = local;
    #pragma unroll
    for (int o = 1; o < 32; o <<= 1) {
        int n = __shfl_up_sync(0xFFFFFFFFu, v, o);
        if (lane >= o) v += n;
    }

    __shared__ int wsum[8];
    if (lane == 31) wsum[wid] = v;
    __syncthreads();
    // scan the 8 warp totals in warp 0
    if (wid == 0 && lane < 8) {
        int s = wsum[lane];
        #pragma unroll
        for (int o = 1; o < 8; o <<= 1) {
            int n = __shfl_up_sync(0xFFu, s, o);
            if (lane >= o) s += n;
        }
        wsum[lane] = s;
    }
    __syncthreads();

    const int base = (v - local) + (wid > 0 ? wsum[wid - 1] : 0); // exclusive @ token 4i

    int4 st;
    st.x = base;
    st.y = base + d.x;
    st.z = st.y + d.y;
    st.w = st.z + d.z;
    ((int4*)(g_start + b * TT))[i] = st;

    if (i == PT - 1) {
        const int total = st.w + d.w;
        const int dlen = min(total, MEL);
        g_dec[b] = dlen;
        if (out_tail) out_tail[b] = (float)dlen;
    }
}

// ---------------------------------------------------------------------------
// Kernel 2: one token per block, 96 threads (one float4 slot each).
// Launched with programmatic stream serialization (PDL): the prologue
// (everything independent of prep) runs concurrently with prep; we only
// cudaGridDependencySynchronize() right before touching g_start / g_dec.
//   blockIdx.x <  TT : token expansion, predicated 7-wide store burst
//   blockIdx.x >= TT : zero the [dec_len, MEL) tail (strided over ZB blocks)
// ---------------------------------------------------------------------------
__global__ void __launch_bounds__(96) expand_kernel(
    const float* __restrict__ enc,     // [B,T,H]
    const float* __restrict__ pitch,   // [B,1,T]
    const float* __restrict__ energy,  // [B,1,T]
    const float* __restrict__ pw,      // [H,1,3]
    const float* __restrict__ pb,      // [H]
    const float* __restrict__ ew,      // [H,1,3]
    const float* __restrict__ eb,      // [H]
    const int*   __restrict__ durations,
    float* __restrict__ out)           // [B,MEL,H]
{
    const int b = blockIdx.y;
    const int q = threadIdx.x;

    if (blockIdx.x >= TT) {
        // ---- zerofill path ----
        const int z = blockIdx.x - TT;
        const float4 zero = make_float4(0.f, 0.f, 0.f, 0.f);
        float4* base = (float4*)out + (long long)b * MEL * H4 + q;
        cudaGridDependencySynchronize();           // need g_dec
        const int dec = g_dec[b];
        for (int j = dec + z; j < MEL; j += ZB)
            __stcs(base + (long long)j * H4, zero);
        return;
    }

    const int t = blockIdx.x;
    const int rep = durations[b * TT + t];         // input, prep-independent
    if (rep <= 0) return;

    // ---- prep-independent prologue (overlaps with prep under PDL) ----
    // enc row (one float4 per thread)
    const float4 e4 = *(const float4*)(enc + ((long long)b * TT + t) * HH + 4 * q);

    // conv windows (SAME, zero pad) — broadcast loads, L1/L2-resident
    const float* pr = pitch  + (long long)b * TT;
    const float* er = energy + (long long)b * TT;
    const float pm1 = (t > 0)      ? pr[t - 1] : 0.f;
    const float p0  =                pr[t];
    const float pp1 = (t < TT - 1) ? pr[t + 1] : 0.f;
    const float em1 = (t > 0)      ? er[t - 1] : 0.f;
    const float e0  =                er[t];
    const float ep1 = (t < TT - 1) ? er[t + 1] : 0.f;

    // weights: [H][3] row-major -> 12 contiguous floats per float4-slot
    const float4* pwv = (const float4*)(pw + 12 * q);
    const float4 w0 = pwv[0], w1 = pwv[1], w2 = pwv[2];
    const float4* ewv = (const float4*)(ew + 12 * q);
    const float4 u0 = ewv[0], u1 = ewv[1], u2 = ewv[2];
    const float4 pbv = ((const float4*)pb)[q];
    const float4 ebv = ((const float4*)eb)[q];

    float4 res;
    res.x = e4.x + pbv.x + ebv.x
          + pm1 * w0.x + p0 * w0.y + pp1 * w0.z
          + em1 * u0.x + e0 * u0.y + ep1 * u0.z;
    res.y = e4.y + pbv.y + ebv.y
          + pm1 * w0.w + p0 * w1.x + pp1 * w1.y
          + em1 * u0.w + e0 * u1.x + ep1 * u1.y;
    res.z = e4.z + pbv.z + ebv.z
          + pm1 * w1.z + p0 * w1.w + pp1 * w2.x
          + em1 * u1.z + e0 * u1.w + ep1 * u2.x;
    res.w = e4.w + pbv.w + ebv.w
          + pm1 * w2.y + p0 * w2.z + pp1 * w2.w
          + em1 * u2.y + e0 * u2.z + ep1 * u2.w;

    // ---- dependent part: wait for prep, then read start and burst-store ----
    cudaGridDependencySynchronize();
    const int start = g_start[b * TT + t];
    const int n = min(start + rep, MEL) - start;
    if (n <= 0) return;

    // predicated store burst: reps < 8, all addresses independent,
    // stores issue back-to-back with no loop-carried dependency
    float4* dst = (float4*)out + ((long long)b * MEL + start) * H4 + q;
    #pragma unroll
    for (int j = 0; j < 7; ++j)
        if (j < n) __stcs(dst + (long long)j * H4, res);
    for (int j = 7; j < n; ++j)          // safety; never taken for this data
        __stcs(dst + (long long)j * H4, res);
}

extern "C" void kernel_launch(void* const* d_in, const int* in_sizes, int n_in,
                              void* d_out, int out_size)
{
    const float* enc    = (const float*)d_in[0];
    const float* pitch  = (const float*)d_in[1];
    const float* energy = (const float*)d_in[2];
    const float* pw     = (const float*)d_in[3];
    const float* pb     = (const float*)d_in[4];
    const float* ew     = (const float*)d_in[5];
    const float* eb     = (const float*)d_in[6];
    const int*   dur    = (const int*)d_in[7];
    float* out = (float*)d_out;

    const long long mainN = (long long)BB * MEL * HH;    // 50,331,648
    float* out_tail = ((long long)out_size >= mainN + BB) ? (out + mainN) : nullptr;

    prep_kernel<<<BB, PT>>>(dur, out_tail);

    // expand launched with programmatic dependent launch: starts while prep
    // is still running; the device-side sync gates only the g_start/g_dec reads.
    cudaLaunchConfig_t cfg = {};
    cfg.gridDim  = dim3(TT + ZB, BB, 1);
    cfg.blockDim = dim3(96, 1, 1);
    cfg.dynamicSmemBytes = 0;
    cfg.stream = 0;   // legacy default stream (matches harness capture)
    cudaLaunchAttribute attrs[1];
    attrs[0].id = cudaLaunchAttributeProgrammaticStreamSerialization;
    attrs[0].val.programmaticStreamSerializationAllowed = 1;
    cfg.attrs = attrs;
    cfg.numAttrs = 1;
    cudaLaunchKernelEx(&cfg, expand_kernel,
                       enc, pitch, energy, pw, pb, ew, eb, dur, out);
}